// round 9
// baseline (speedup 1.0000x reference)
#include <cuda_runtime.h>
#include <math.h>

#define NPTS 512
#define DCLS 9
#define LLAT 32
#define MAXB 256
#define EF 20        // floats per entry (4 points SoA: x0-3,y0-3,z0-3,w0-3,n0-3)
#define NQRT 4       // candidate quarters
#define CAND_Q 128   // candidates per quarter
#define ENT_Q 32     // entries per quarter
#define CE 4         // entries per chunk (16 candidates)
#define NCHUNK1 8    // chunks per quarter
#define QPT 4

typedef unsigned long long u64;

// scratch: per (b, side, quarter, query): (partial min, partial sdot); per (b, side) histogram
__device__ float2 g_ms[MAXB * 2 * NQRT * NPTS];
__device__ int    g_hist[MAXB * 2 * DCLS];
__device__ unsigned int g_cnt[MAXB];   // zero-init; finisher resets each call

__device__ __forceinline__ u64 ffma2(u64 a, u64 b, u64 c) {
    u64 d; asm("fma.rn.f32x2 %0,%1,%2,%3;" : "=l"(d) : "l"(a), "l"(b), "l"(c)); return d;
}
__device__ __forceinline__ u64 fmul2(u64 a, u64 b) {
    u64 d; asm("mul.rn.f32x2 %0,%1,%2;" : "=l"(d) : "l"(a), "l"(b)); return d;
}
__device__ __forceinline__ u64 fadd2(u64 a, u64 b) {
    u64 d; asm("add.rn.f32x2 %0,%1,%2;" : "=l"(d) : "l"(a), "l"(b)); return d;
}
__device__ __forceinline__ u64 pack2(float lo, float hi) {
    u64 r; asm("mov.b64 %0,{%1,%2};" : "=l"(r) : "f"(lo), "f"(hi)); return r;
}
__device__ __forceinline__ float2 unpack2(u64 v) {
    float2 r; asm("mov.b64 {%0,%1},%2;" : "=f"(r.x), "=f"(r.y) : "l"(v)); return r;
}

__device__ __forceinline__ float warpReduceSum(float v) {
    #pragma unroll
    for (int o = 16; o > 0; o >>= 1)
        v += __shfl_down_sync(0xFFFFFFFFu, v, o);
    return v;
}

// Rescan winning chunk (bit-identical arithmetic) for first-occurrence local index.
__device__ __noinline__ int rescan_chunk(const float* __restrict__ sarr,
                                         int ch, float target, float4 q, float qn)
{
    const u64 qx = pack2(q.x, q.x), qy = pack2(q.y, q.y);
    const u64 qz = pack2(q.z, q.z), qw = pack2(q.w, q.w);
    const u64 qc = pack2(qn, qn);
    const u64 M2 = pack2(-2.0f, -2.0f);
    const ulonglong2* cp = reinterpret_cast<const ulonglong2*>(sarr + ch * (CE * EF));
    int id = -1;
    #pragma unroll
    for (int e = 0; e < CE; e++) {
        ulonglong2 vx = cp[e * 5 + 0], vy = cp[e * 5 + 1], vz = cp[e * 5 + 2],
                   vw = cp[e * 5 + 3], vn = cp[e * 5 + 4];
        u64 d0 = ffma2(qw, vw.x, ffma2(qz, vz.x, ffma2(qy, vy.x, fmul2(qx, vx.x))));
        u64 v0 = ffma2(M2, d0, fadd2(qc, vn.x));
        u64 d1 = ffma2(qw, vw.y, ffma2(qz, vz.y, ffma2(qy, vy.y, fmul2(qx, vx.y))));
        u64 v1 = ffma2(M2, d1, fadd2(qc, vn.y));
        float2 a = unpack2(v0);
        float2 d = unpack2(v1);
        int base = ch * (CE * 4) + e * 4;
        if (id < 0 && a.x == target) id = base + 0;
        if (id < 0 && a.y == target) id = base + 1;
        if (id < 0 && d.x == target) id = base + 2;
        if (id < 0 && d.y == target) id = base + 3;
    }
    return (id < 0) ? 0 : id;
}

// grid = (B, 2 sides, 4 quarters), block = 128. Last CTA per batch finalizes.
__global__ __launch_bounds__(128, 8) void nn_kernel(
    const float* __restrict__ kine_input,
    const float* __restrict__ class_input,
    const float* __restrict__ kine_pred,
    const float* __restrict__ class_pred,
    const float* __restrict__ mu,
    const float* __restrict__ log_var,
    float* __restrict__ out)
{
    const int b = blockIdx.x, side = blockIdx.y, quarter = blockIdx.z;
    const int t = threadIdx.x;

    const float* qk = (side == 0) ? kine_input : kine_pred;
    const float* ck = (side == 0) ? kine_pred  : kine_input;
    const float* cl = (side == 0) ? class_input : class_pred;  // own-side class rows
    const float* cg = (side == 0) ? class_pred  : class_input; // candidate-side class rows

    __shared__ __align__(16) float sc[ENT_Q * EF];  // 2.5KB candidate quarter
    __shared__ int sh[DCLS];
    __shared__ unsigned int s_last;
    __shared__ float red[4];

    if (quarter == 0 && t < DCLS) sh[t] = 0;

    // ---- stage candidate quarter (1 point per thread) ----
    if (t < CAND_Q) {
        float4 v = reinterpret_cast<const float4*>(ck)[b * NPTS + quarter * CAND_Q + t];
        float n = v.x * v.x + v.y * v.y + v.z * v.z + v.w * v.w;
        int e = t >> 2, l = t & 3;
        float* ba = sc + e * EF;
        ba[l] = v.x; ba[4 + l] = v.y; ba[8 + l] = v.z; ba[12 + l] = v.w; ba[16 + l] = n;
    }

    // ---- labels/histogram: only quarter-0 CTAs, own side's 512 class rows ----
    int lab[4];
    if (quarter == 0) {
        #pragma unroll
        for (int r = 0; r < 4; r++) {
            const float* row = cl + ((size_t)b * NPTS + t + 128 * r) * DCLS;
            int li = 0; float mi = row[0];
            #pragma unroll
            for (int d = 1; d < DCLS; d++) {
                float a = row[d];
                if (a > mi) { mi = a; li = d; }
            }
            lab[r] = li;
        }
    }

    __syncthreads();

    if (quarter == 0) {
        #pragma unroll
        for (int r = 0; r < 4; r++) atomicAdd(&sh[lab[r]], 1);
    }

    // ---- scan: 4 queries per thread over 128 candidates ----
    float gmin[QPT]; int gch[QPT];
    #pragma unroll
    for (int qi = 0; qi < QPT; qi++) { gmin[qi] = 3.402823466e38f; gch[qi] = 0; }

    {
        u64 qx[QPT], qy[QPT], qz[QPT], qw[QPT], qc[QPT];
        #pragma unroll
        for (int qi = 0; qi < QPT; qi++) {
            float4 q = reinterpret_cast<const float4*>(qk)[b * NPTS + t + 128 * qi];
            float n = q.x * q.x + q.y * q.y + q.z * q.z + q.w * q.w;
            qx[qi] = pack2(q.x, q.x); qy[qi] = pack2(q.y, q.y);
            qz[qi] = pack2(q.z, q.z); qw[qi] = pack2(q.w, q.w);
            qc[qi] = pack2(n, n);
        }
        const u64 M2 = pack2(-2.0f, -2.0f);

        #pragma unroll 1
        for (int c = 0; c < NCHUNK1; c++) {
            float cm[QPT];
            #pragma unroll
            for (int qi = 0; qi < QPT; qi++) cm[qi] = 3.402823466e38f;
            const ulonglong2* cp = reinterpret_cast<const ulonglong2*>(sc + c * (CE * EF));
            #pragma unroll 1
            for (int e = 0; e < CE; e++) {
                ulonglong2 vx = cp[e * 5 + 0], vy = cp[e * 5 + 1], vz = cp[e * 5 + 2],
                           vw = cp[e * 5 + 3], vn = cp[e * 5 + 4];
                #pragma unroll
                for (int qi = 0; qi < QPT; qi++) {
                    u64 d0 = ffma2(qw[qi], vw.x, ffma2(qz[qi], vz.x, ffma2(qy[qi], vy.x, fmul2(qx[qi], vx.x))));
                    u64 v0 = ffma2(M2, d0, fadd2(qc[qi], vn.x));
                    u64 d1 = ffma2(qw[qi], vw.y, ffma2(qz[qi], vz.y, ffma2(qy[qi], vy.y, fmul2(qx[qi], vx.y))));
                    u64 v1 = ffma2(M2, d1, fadd2(qc[qi], vn.y));
                    float2 a = unpack2(v0);
                    float2 d = unpack2(v1);
                    cm[qi] = fminf(cm[qi], fminf(fminf(a.x, a.y), fminf(d.x, d.y)));
                }
            }
            #pragma unroll
            for (int qi = 0; qi < QPT; qi++)
                if (cm[qi] < gmin[qi]) { gmin[qi] = cm[qi]; gch[qi] = c; }
        }
    }

    // ---- epilogue: rescan for index, gather class rows, write (min, sdot) ----
    const int slotbase = ((b * 2 + side) * NQRT + quarter) * NPTS;
    #pragma unroll 1
    for (int qi = 0; qi < QPT; qi++) {
        float4 q = reinterpret_cast<const float4*>(qk)[b * NPTS + t + 128 * qi];
        float n = q.x * q.x + q.y * q.y + q.z * q.z + q.w * q.w;
        int lidx = rescan_chunk(sc, gch[qi], gmin[qi], q, n);
        int gidx = quarter * CAND_Q + lidx;

        const float* grow = cg + ((size_t)b * NPTS + gidx) * DCLS;
        const float* orow = cl + ((size_t)b * NPTS + t + 128 * qi) * DCLS;
        float sdot = 0.0f;
        #pragma unroll
        for (int d = 0; d < DCLS; d++) sdot = fmaf(grow[d], orow[d], sdot);

        g_ms[slotbase + t + 128 * qi] = make_float2(gmin[qi], sdot);
    }

    if (quarter == 0) {
        __syncthreads();
        if (t < DCLS) g_hist[(b * 2 + side) * DCLS + t] = sh[t];
    }

    // ---- last-CTA-per-batch finalization (8 CTAs per batch) ----
    __syncthreads();
    __threadfence();
    if (t == 0) s_last = atomicAdd(&g_cnt[b], 1u);
    __syncthreads();
    if (s_last != 2u * NQRT - 1u) return;

    __threadfence();   // acquire

    // merge quarters + reduce: 1024 (side,query) pairs, 8 per thread
    float r = 0.0f;
    #pragma unroll
    for (int j = 0; j < 8; j++) {
        int s = t + 128 * j;          // 0..1023
        int sd = s >> 9;
        int q = s & (NPTS - 1);
        int base = ((b * 2 + sd) * NQRT) * NPTS + q;
        float2 best = g_ms[base];
        #pragma unroll
        for (int qq = 1; qq < NQRT; qq++) {
            float2 h = g_ms[base + qq * NPTS];
            if (h.x < best.x) best = h;   // strict <: ties keep lower quarter (first occurrence)
        }
        r += fmaxf(best.x, 0.0f) - best.y;
    }

    const int lane = t & 31;
    const int wid  = t >> 5;
    float v = warpReduceSum(r);
    if (lane == 0) red[wid] = v;
    __syncthreads();
    if (wid == 0) {
        v = (lane < 4) ? red[lane] : 0.0f;
        v = warpReduceSum(v);
        if (lane == 0) {
            float S = v;

            const int* hi = g_hist + (b * 2 + 0) * DCLS;
            const int* hp = g_hist + (b * 2 + 1) * DCLS;
            float cn;
            {
                float d0 = fabsf((float)(hp[0] - hi[0]));
                float d8 = fabsf((float)(hp[DCLS - 1] - hi[DCLS - 1]));
                cn = d0 * 2.0f + d8 * 100.0f;
                #pragma unroll
                for (int c = 1; c < DCLS - 1; c++)
                    cn += fabsf((float)(hp[c] - hi[c]));
            }

            float kl = 0.0f;
            const float* mub = mu      + (size_t)b * LLAT;
            const float* lvb = log_var + (size_t)b * LLAT;
            #pragma unroll
            for (int l = 0; l < LLAT; l++) {
                float m  = mub[l];
                float lv = lvb[l];
                kl += 1.0f + lv - m * m - expf(lv);
            }
            kl = -0.5f * kl;

            out[b] = 0.99f * (S + 0.001f * cn) + 0.01f * kl;

            g_cnt[b] = 0u;   // reset for next graph replay
        }
    }
}

extern "C" void kernel_launch(void* const* d_in, const int* in_sizes, int n_in,
                              void* d_out, int out_size)
{
    const float* kine_input  = (const float*)d_in[0];
    const float* class_input = (const float*)d_in[1];
    const float* kine_pred   = (const float*)d_in[2];
    const float* class_pred  = (const float*)d_in[3];
    const float* mu          = (const float*)d_in[4];
    const float* log_var     = (const float*)d_in[5];

    const int B = in_sizes[4] / LLAT;   // mu is [B, 32]

    nn_kernel<<<dim3(B, 2, NQRT), 128>>>(kine_input, class_input, kine_pred, class_pred,
                                         mu, log_var, (float*)d_out);
}

// round 10
// speedup vs baseline: 1.1424x; 1.1424x over previous
#include <cuda_runtime.h>
#include <math.h>

#define NPTS 512
#define DCLS 9
#define LLAT 32
#define MAXB 256
#define EF 20        // floats per entry (4 points SoA: x0-3,y0-3,z0-3,w0-3,n0-3)
#define CAND_HALF 256
#define ENT_HALF 64
#define CE 4         // entries per chunk (16 candidates)
#define NCHUNK1 16   // chunks per half
#define QPT 8
#define THREADS 64

typedef unsigned long long u64;

// scratch: per (b, side, half, query): (partial min, partial sdot); per (b, side) histogram
__device__ float2 g_ms[MAXB * 2 * 2 * NPTS];
__device__ int    g_hist[MAXB * 2 * DCLS];
__device__ unsigned int g_cnt[MAXB];   // zero-init; finisher resets each call

__device__ __forceinline__ u64 ffma2(u64 a, u64 b, u64 c) {
    u64 d; asm("fma.rn.f32x2 %0,%1,%2,%3;" : "=l"(d) : "l"(a), "l"(b), "l"(c)); return d;
}
__device__ __forceinline__ u64 fmul2(u64 a, u64 b) {
    u64 d; asm("mul.rn.f32x2 %0,%1,%2;" : "=l"(d) : "l"(a), "l"(b)); return d;
}
__device__ __forceinline__ u64 fadd2(u64 a, u64 b) {
    u64 d; asm("add.rn.f32x2 %0,%1,%2;" : "=l"(d) : "l"(a), "l"(b)); return d;
}
__device__ __forceinline__ u64 pack2(float lo, float hi) {
    u64 r; asm("mov.b64 %0,{%1,%2};" : "=l"(r) : "f"(lo), "f"(hi)); return r;
}
__device__ __forceinline__ float2 unpack2(u64 v) {
    float2 r; asm("mov.b64 {%0,%1},%2;" : "=f"(r.x), "=f"(r.y) : "l"(v)); return r;
}

__device__ __forceinline__ float warpReduceSum(float v) {
    #pragma unroll
    for (int o = 16; o > 0; o >>= 1)
        v += __shfl_down_sync(0xFFFFFFFFu, v, o);
    return v;
}

// Rescan winning chunk (bit-identical arithmetic) for first-occurrence local index.
__device__ __noinline__ int rescan_chunk(const float* __restrict__ sarr,
                                         int ch, float target, float4 q, float qn)
{
    const u64 qx = pack2(q.x, q.x), qy = pack2(q.y, q.y);
    const u64 qz = pack2(q.z, q.z), qw = pack2(q.w, q.w);
    const u64 qc = pack2(qn, qn);
    const u64 M2 = pack2(-2.0f, -2.0f);
    const ulonglong2* cp = reinterpret_cast<const ulonglong2*>(sarr + ch * (CE * EF));
    int id = -1;
    #pragma unroll
    for (int e = 0; e < CE; e++) {
        ulonglong2 vx = cp[e * 5 + 0], vy = cp[e * 5 + 1], vz = cp[e * 5 + 2],
                   vw = cp[e * 5 + 3], vn = cp[e * 5 + 4];
        u64 d0 = ffma2(qw, vw.x, ffma2(qz, vz.x, ffma2(qy, vy.x, fmul2(qx, vx.x))));
        u64 v0 = ffma2(M2, d0, fadd2(qc, vn.x));
        u64 d1 = ffma2(qw, vw.y, ffma2(qz, vz.y, ffma2(qy, vy.y, fmul2(qx, vx.y))));
        u64 v1 = ffma2(M2, d1, fadd2(qc, vn.y));
        float2 a = unpack2(v0);
        float2 d = unpack2(v1);
        int base = ch * (CE * 4) + e * 4;
        if (id < 0 && a.x == target) id = base + 0;
        if (id < 0 && a.y == target) id = base + 1;
        if (id < 0 && d.x == target) id = base + 2;
        if (id < 0 && d.y == target) id = base + 3;
    }
    return (id < 0) ? 0 : id;
}

// grid = (B, 2 sides, 2 halves), block = 64, 8 queries/thread. Last CTA per batch finalizes.
__global__ void nn_kernel(
    const float* __restrict__ kine_input,
    const float* __restrict__ class_input,
    const float* __restrict__ kine_pred,
    const float* __restrict__ class_pred,
    const float* __restrict__ mu,
    const float* __restrict__ log_var,
    float* __restrict__ out)
{
    const int b = blockIdx.x, side = blockIdx.y, half = blockIdx.z;
    const int t = threadIdx.x;

    const float* qk = (side == 0) ? kine_input : kine_pred;
    const float* ck = (side == 0) ? kine_pred  : kine_input;
    const float* cl = (side == 0) ? class_input : class_pred;  // own-side class rows
    const float* cg = (side == 0) ? class_pred  : class_input; // candidate-side class rows

    __shared__ __align__(16) float sc[ENT_HALF * EF];  // 5KB candidate half
    __shared__ int sh[DCLS];
    __shared__ unsigned int s_last;
    __shared__ float red[2];

    if (half == 0 && t < DCLS) sh[t] = 0;

    // ---- stage candidate half (4 points per thread) ----
    #pragma unroll
    for (int p = t; p < CAND_HALF; p += THREADS) {
        float4 v = reinterpret_cast<const float4*>(ck)[b * NPTS + half * CAND_HALF + p];
        float n = v.x * v.x + v.y * v.y + v.z * v.z + v.w * v.w;
        int e = p >> 2, l = p & 3;
        float* ba = sc + e * EF;
        ba[l] = v.x; ba[4 + l] = v.y; ba[8 + l] = v.z; ba[12 + l] = v.w; ba[16 + l] = n;
    }

    // ---- labels/histogram: only half-0 CTAs, own side's 512 class rows (8/thread) ----
    int lab[8];
    if (half == 0) {
        #pragma unroll
        for (int r = 0; r < 8; r++) {
            const float* row = cl + ((size_t)b * NPTS + t + THREADS * r) * DCLS;
            int li = 0; float mi = row[0];
            #pragma unroll
            for (int d = 1; d < DCLS; d++) {
                float a = row[d];
                if (a > mi) { mi = a; li = d; }
            }
            lab[r] = li;
        }
    }

    __syncthreads();

    if (half == 0) {
        #pragma unroll
        for (int r = 0; r < 8; r++) atomicAdd(&sh[lab[r]], 1);
    }

    // ---- scan: 8 queries per thread over 256 candidates ----
    float gmin[QPT]; int gch[QPT];
    #pragma unroll
    for (int qi = 0; qi < QPT; qi++) { gmin[qi] = 3.402823466e38f; gch[qi] = 0; }

    {
        u64 qx[QPT], qy[QPT], qz[QPT], qw[QPT], qc[QPT];
        #pragma unroll
        for (int qi = 0; qi < QPT; qi++) {
            float4 q = reinterpret_cast<const float4*>(qk)[b * NPTS + t + THREADS * qi];
            float n = q.x * q.x + q.y * q.y + q.z * q.z + q.w * q.w;
            qx[qi] = pack2(q.x, q.x); qy[qi] = pack2(q.y, q.y);
            qz[qi] = pack2(q.z, q.z); qw[qi] = pack2(q.w, q.w);
            qc[qi] = pack2(n, n);
        }
        const u64 M2 = pack2(-2.0f, -2.0f);

        #pragma unroll 1
        for (int c = 0; c < NCHUNK1; c++) {
            float cm[QPT];
            #pragma unroll
            for (int qi = 0; qi < QPT; qi++) cm[qi] = 3.402823466e38f;
            const ulonglong2* cp = reinterpret_cast<const ulonglong2*>(sc + c * (CE * EF));
            #pragma unroll 1
            for (int e = 0; e < CE; e++) {
                ulonglong2 vx = cp[e * 5 + 0], vy = cp[e * 5 + 1], vz = cp[e * 5 + 2],
                           vw = cp[e * 5 + 3], vn = cp[e * 5 + 4];
                #pragma unroll
                for (int qi = 0; qi < QPT; qi++) {
                    u64 d0 = ffma2(qw[qi], vw.x, ffma2(qz[qi], vz.x, ffma2(qy[qi], vy.x, fmul2(qx[qi], vx.x))));
                    u64 v0 = ffma2(M2, d0, fadd2(qc[qi], vn.x));
                    u64 d1 = ffma2(qw[qi], vw.y, ffma2(qz[qi], vz.y, ffma2(qy[qi], vy.y, fmul2(qx[qi], vx.y))));
                    u64 v1 = ffma2(M2, d1, fadd2(qc[qi], vn.y));
                    float2 a = unpack2(v0);
                    float2 d = unpack2(v1);
                    cm[qi] = fminf(cm[qi], fminf(fminf(a.x, a.y), fminf(d.x, d.y)));
                }
            }
            #pragma unroll
            for (int qi = 0; qi < QPT; qi++)
                if (cm[qi] < gmin[qi]) { gmin[qi] = cm[qi]; gch[qi] = c; }
        }
    }   // packed queries die here

    // ---- epilogue: rescan for index, gather class rows, write (min, sdot) ----
    const int slotbase = ((b * 2 + side) * 2 + half) * NPTS;
    #pragma unroll 1
    for (int qi = 0; qi < QPT; qi++) {
        float4 q = reinterpret_cast<const float4*>(qk)[b * NPTS + t + THREADS * qi];
        float n = q.x * q.x + q.y * q.y + q.z * q.z + q.w * q.w;
        int lidx = rescan_chunk(sc, gch[qi], gmin[qi], q, n);
        int gidx = half * CAND_HALF + lidx;

        const float* grow = cg + ((size_t)b * NPTS + gidx) * DCLS;
        const float* orow = cl + ((size_t)b * NPTS + t + THREADS * qi) * DCLS;
        float sdot = 0.0f;
        #pragma unroll
        for (int d = 0; d < DCLS; d++) sdot = fmaf(grow[d], orow[d], sdot);

        g_ms[slotbase + t + THREADS * qi] = make_float2(gmin[qi], sdot);
    }

    if (half == 0) {
        __syncthreads();
        if (t < DCLS) g_hist[(b * 2 + side) * DCLS + t] = sh[t];
    }

    // ---- last-CTA-per-batch finalization (4 CTAs per batch) ----
    __syncthreads();
    __threadfence();
    if (t == 0) s_last = atomicAdd(&g_cnt[b], 1u);
    __syncthreads();
    if (s_last != 3u) return;

    __threadfence();   // acquire

    // merge halves + reduce: 1024 (side,query) pairs, 16 per thread
    float r = 0.0f;
    #pragma unroll
    for (int j = 0; j < 16; j++) {
        int s = t + THREADS * j;      // 0..1023
        int sd = s >> 9;
        int q = s & (NPTS - 1);
        int base = ((b * 2 + sd) * 2) * NPTS + q;
        float2 h0 = g_ms[base];
        float2 h1 = g_ms[base + NPTS];
        float m, sv;
        if (h0.x <= h1.x) { m = h0.x; sv = h0.y; } else { m = h1.x; sv = h1.y; }
        r += fmaxf(m, 0.0f) - sv;
    }

    const int lane = t & 31;
    const int wid  = t >> 5;
    float v = warpReduceSum(r);
    if (lane == 0) red[wid] = v;
    __syncthreads();
    if (wid == 0) {
        v = (lane < 2) ? red[lane] : 0.0f;
        v = warpReduceSum(v);
        if (lane == 0) {
            float S = v;

            const int* hi = g_hist + (b * 2 + 0) * DCLS;
            const int* hp = g_hist + (b * 2 + 1) * DCLS;
            float cn;
            {
                float d0 = fabsf((float)(hp[0] - hi[0]));
                float d8 = fabsf((float)(hp[DCLS - 1] - hi[DCLS - 1]));
                cn = d0 * 2.0f + d8 * 100.0f;
                #pragma unroll
                for (int c = 1; c < DCLS - 1; c++)
                    cn += fabsf((float)(hp[c] - hi[c]));
            }

            float kl = 0.0f;
            const float* mub = mu      + (size_t)b * LLAT;
            const float* lvb = log_var + (size_t)b * LLAT;
            #pragma unroll
            for (int l = 0; l < LLAT; l++) {
                float m  = mub[l];
                float lv = lvb[l];
                kl += 1.0f + lv - m * m - expf(lv);
            }
            kl = -0.5f * kl;

            out[b] = 0.99f * (S + 0.001f * cn) + 0.01f * kl;

            g_cnt[b] = 0u;   // reset for next graph replay
        }
    }
}

extern "C" void kernel_launch(void* const* d_in, const int* in_sizes, int n_in,
                              void* d_out, int out_size)
{
    const float* kine_input  = (const float*)d_in[0];
    const float* class_input = (const float*)d_in[1];
    const float* kine_pred   = (const float*)d_in[2];
    const float* class_pred  = (const float*)d_in[3];
    const float* mu          = (const float*)d_in[4];
    const float* log_var     = (const float*)d_in[5];

    const int B = in_sizes[4] / LLAT;   // mu is [B, 32]

    nn_kernel<<<dim3(B, 2, 2), THREADS>>>(kine_input, class_input, kine_pred, class_pred,
                                          mu, log_var, (float*)d_out);
}

// round 11
// speedup vs baseline: 1.2389x; 1.0844x over previous
#include <cuda_runtime.h>
#include <math.h>

#define NPTS 512
#define DCLS 9
#define LLAT 32
#define MAXB 256
#define EF 20        // floats per entry (4 points SoA: x0-3,y0-3,z0-3,w0-3,n0-3)
#define CAND_HALF 256
#define ENT_HALF 64
#define CE 4         // entries per chunk (16 candidates)
#define NCHUNK1 16   // chunks per half
#define QPT 4

typedef unsigned long long u64;

// scratch: per (b, side, half, query): (partial min, partial sdot); per (b, side) histogram
__device__ float2 g_ms[MAXB * 2 * 2 * NPTS];
__device__ int    g_hist[MAXB * 2 * DCLS];
__device__ unsigned int g_cnt[MAXB];   // zero-init; finisher resets each call

__device__ __forceinline__ u64 ffma2(u64 a, u64 b, u64 c) {
    u64 d; asm("fma.rn.f32x2 %0,%1,%2,%3;" : "=l"(d) : "l"(a), "l"(b), "l"(c)); return d;
}
__device__ __forceinline__ u64 fmul2(u64 a, u64 b) {
    u64 d; asm("mul.rn.f32x2 %0,%1,%2;" : "=l"(d) : "l"(a), "l"(b)); return d;
}
__device__ __forceinline__ u64 fadd2(u64 a, u64 b) {
    u64 d; asm("add.rn.f32x2 %0,%1,%2;" : "=l"(d) : "l"(a), "l"(b)); return d;
}
__device__ __forceinline__ u64 pack2(float lo, float hi) {
    u64 r; asm("mov.b64 %0,{%1,%2};" : "=l"(r) : "f"(lo), "f"(hi)); return r;
}
__device__ __forceinline__ float2 unpack2(u64 v) {
    float2 r; asm("mov.b64 {%0,%1},%2;" : "=f"(r.x), "=f"(r.y) : "l"(v)); return r;
}

__device__ __forceinline__ float warpReduceSum(float v) {
    #pragma unroll
    for (int o = 16; o > 0; o >>= 1)
        v += __shfl_down_sync(0xFFFFFFFFu, v, o);
    return v;
}

// Rescan winning chunk (bit-identical arithmetic) for first-occurrence local index.
__device__ __noinline__ int rescan_chunk(const float* __restrict__ sarr,
                                         int ch, float target, float4 q, float qn)
{
    const u64 qx = pack2(q.x, q.x), qy = pack2(q.y, q.y);
    const u64 qz = pack2(q.z, q.z), qw = pack2(q.w, q.w);
    const u64 qc = pack2(qn, qn);
    const u64 M2 = pack2(-2.0f, -2.0f);
    const ulonglong2* cp = reinterpret_cast<const ulonglong2*>(sarr + ch * (CE * EF));
    int id = -1;
    #pragma unroll
    for (int e = 0; e < CE; e++) {
        ulonglong2 vx = cp[e * 5 + 0], vy = cp[e * 5 + 1], vz = cp[e * 5 + 2],
                   vw = cp[e * 5 + 3], vn = cp[e * 5 + 4];
        u64 d0 = ffma2(qw, vw.x, ffma2(qz, vz.x, ffma2(qy, vy.x, fmul2(qx, vx.x))));
        u64 v0 = ffma2(M2, d0, fadd2(qc, vn.x));
        u64 d1 = ffma2(qw, vw.y, ffma2(qz, vz.y, ffma2(qy, vy.y, fmul2(qx, vx.y))));
        u64 v1 = ffma2(M2, d1, fadd2(qc, vn.y));
        float2 a = unpack2(v0);
        float2 d = unpack2(v1);
        int base = ch * (CE * 4) + e * 4;
        if (id < 0 && a.x == target) id = base + 0;
        if (id < 0 && a.y == target) id = base + 1;
        if (id < 0 && d.x == target) id = base + 2;
        if (id < 0 && d.y == target) id = base + 3;
    }
    return (id < 0) ? 0 : id;
}

// grid = (B, 2 sides, 2 halves), block = 128. Last CTA per batch finalizes.
__global__ __launch_bounds__(128, 6) void nn_kernel(
    const float* __restrict__ kine_input,
    const float* __restrict__ class_input,
    const float* __restrict__ kine_pred,
    const float* __restrict__ class_pred,
    const float* __restrict__ mu,
    const float* __restrict__ log_var,
    float* __restrict__ out)
{
    const int b = blockIdx.x, side = blockIdx.y, half = blockIdx.z;
    const int t = threadIdx.x;

    const float* qk = (side == 0) ? kine_input : kine_pred;
    const float* ck = (side == 0) ? kine_pred  : kine_input;
    const float* cl = (side == 0) ? class_input : class_pred;  // own-side class rows
    const float* cg = (side == 0) ? class_pred  : class_input; // candidate-side class rows

    __shared__ __align__(16) float sc[ENT_HALF * EF];  // 5KB candidate half
    __shared__ int sh[DCLS];
    __shared__ unsigned int s_last;
    __shared__ float red[4];

    if (half == 0 && t < DCLS) sh[t] = 0;

    // ---- stage candidate half (2 points per thread) ----
    #pragma unroll
    for (int p = t; p < CAND_HALF; p += 128) {
        float4 v = reinterpret_cast<const float4*>(ck)[b * NPTS + half * CAND_HALF + p];
        float n = v.x * v.x + v.y * v.y + v.z * v.z + v.w * v.w;
        int e = p >> 2, l = p & 3;
        float* ba = sc + e * EF;
        ba[l] = v.x; ba[4 + l] = v.y; ba[8 + l] = v.z; ba[12 + l] = v.w; ba[16 + l] = n;
    }

    // ---- labels/histogram: only half-0 CTAs, own side's 512 class rows ----
    int lab[4];
    if (half == 0) {
        #pragma unroll
        for (int r = 0; r < 4; r++) {
            const float* row = cl + ((size_t)b * NPTS + t + 128 * r) * DCLS;
            int li = 0; float mi = row[0];
            #pragma unroll
            for (int d = 1; d < DCLS; d++) {
                float a = row[d];
                if (a > mi) { mi = a; li = d; }
            }
            lab[r] = li;
        }
    }

    __syncthreads();

    if (half == 0) {
        #pragma unroll
        for (int r = 0; r < 4; r++) atomicAdd(&sh[lab[r]], 1);
    }

    // ---- scan: 4 queries per thread over 256 candidates ----
    float gmin[QPT]; int gch[QPT];
    #pragma unroll
    for (int qi = 0; qi < QPT; qi++) { gmin[qi] = 3.402823466e38f; gch[qi] = 0; }

    {
        u64 qx[QPT], qy[QPT], qz[QPT], qw[QPT], qc[QPT];
        #pragma unroll
        for (int qi = 0; qi < QPT; qi++) {
            float4 q = reinterpret_cast<const float4*>(qk)[b * NPTS + t + 128 * qi];
            float n = q.x * q.x + q.y * q.y + q.z * q.z + q.w * q.w;
            qx[qi] = pack2(q.x, q.x); qy[qi] = pack2(q.y, q.y);
            qz[qi] = pack2(q.z, q.z); qw[qi] = pack2(q.w, q.w);
            qc[qi] = pack2(n, n);
        }
        const u64 M2 = pack2(-2.0f, -2.0f);

        #pragma unroll 1
        for (int c = 0; c < NCHUNK1; c++) {
            float cm[QPT];
            #pragma unroll
            for (int qi = 0; qi < QPT; qi++) cm[qi] = 3.402823466e38f;
            const ulonglong2* cp = reinterpret_cast<const ulonglong2*>(sc + c * (CE * EF));
            #pragma unroll 2
            for (int e = 0; e < CE; e++) {
                ulonglong2 vx = cp[e * 5 + 0], vy = cp[e * 5 + 1], vz = cp[e * 5 + 2],
                           vw = cp[e * 5 + 3], vn = cp[e * 5 + 4];
                #pragma unroll
                for (int qi = 0; qi < QPT; qi++) {
                    u64 d0 = ffma2(qw[qi], vw.x, ffma2(qz[qi], vz.x, ffma2(qy[qi], vy.x, fmul2(qx[qi], vx.x))));
                    u64 v0 = ffma2(M2, d0, fadd2(qc[qi], vn.x));
                    u64 d1 = ffma2(qw[qi], vw.y, ffma2(qz[qi], vz.y, ffma2(qy[qi], vy.y, fmul2(qx[qi], vx.y))));
                    u64 v1 = ffma2(M2, d1, fadd2(qc[qi], vn.y));
                    float2 a = unpack2(v0);
                    float2 d = unpack2(v1);
                    cm[qi] = fminf(cm[qi], fminf(fminf(a.x, a.y), fminf(d.x, d.y)));
                }
            }
            #pragma unroll
            for (int qi = 0; qi < QPT; qi++)
                if (cm[qi] < gmin[qi]) { gmin[qi] = cm[qi]; gch[qi] = c; }
        }
    }   // packed queries die here

    // ---- epilogue: rescan for index, gather class rows, write (min, sdot) ----
    const int slotbase = ((b * 2 + side) * 2 + half) * NPTS;
    #pragma unroll 1
    for (int qi = 0; qi < QPT; qi++) {
        float4 q = reinterpret_cast<const float4*>(qk)[b * NPTS + t + 128 * qi];
        float n = q.x * q.x + q.y * q.y + q.z * q.z + q.w * q.w;
        int lidx = rescan_chunk(sc, gch[qi], gmin[qi], q, n);
        int gidx = half * CAND_HALF + lidx;

        const float* grow = cg + ((size_t)b * NPTS + gidx) * DCLS;
        const float* orow = cl + ((size_t)b * NPTS + t + 128 * qi) * DCLS;
        float sdot = 0.0f;
        #pragma unroll
        for (int d = 0; d < DCLS; d++) sdot = fmaf(grow[d], orow[d], sdot);

        g_ms[slotbase + t + 128 * qi] = make_float2(gmin[qi], sdot);
    }

    if (half == 0) {
        __syncthreads();
        if (t < DCLS) g_hist[(b * 2 + side) * DCLS + t] = sh[t];
    }

    // ---- last-CTA-per-batch finalization (4 CTAs per batch) ----
    __syncthreads();
    __threadfence();
    if (t == 0) s_last = atomicAdd(&g_cnt[b], 1u);
    __syncthreads();
    if (s_last != 3u) return;

    __threadfence();   // acquire

    // merge halves + reduce: 1024 (side,query) pairs, 8 per thread
    float r = 0.0f;
    #pragma unroll
    for (int j = 0; j < 8; j++) {
        int s = t + 128 * j;          // 0..1023
        int sd = s >> 9;
        int q = s & (NPTS - 1);
        int base = ((b * 2 + sd) * 2) * NPTS + q;
        float2 h0 = g_ms[base];
        float2 h1 = g_ms[base + NPTS];
        float m, sv;
        if (h0.x <= h1.x) { m = h0.x; sv = h0.y; } else { m = h1.x; sv = h1.y; }
        r += fmaxf(m, 0.0f) - sv;
    }

    const int lane = t & 31;
    const int wid  = t >> 5;
    float v = warpReduceSum(r);
    if (lane == 0) red[wid] = v;
    __syncthreads();
    if (wid == 0) {
        v = (lane < 4) ? red[lane] : 0.0f;
        v = warpReduceSum(v);
        if (lane == 0) {
            float S = v;

            const int* hi = g_hist + (b * 2 + 0) * DCLS;
            const int* hp = g_hist + (b * 2 + 1) * DCLS;
            float cn;
            {
                float d0 = fabsf((float)(hp[0] - hi[0]));
                float d8 = fabsf((float)(hp[DCLS - 1] - hi[DCLS - 1]));
                cn = d0 * 2.0f + d8 * 100.0f;
                #pragma unroll
                for (int c = 1; c < DCLS - 1; c++)
                    cn += fabsf((float)(hp[c] - hi[c]));
            }

            float kl = 0.0f;
            const float* mub = mu      + (size_t)b * LLAT;
            const float* lvb = log_var + (size_t)b * LLAT;
            #pragma unroll
            for (int l = 0; l < LLAT; l++) {
                float m  = mub[l];
                float lv = lvb[l];
                kl += 1.0f + lv - m * m - expf(lv);
            }
            kl = -0.5f * kl;

            out[b] = 0.99f * (S + 0.001f * cn) + 0.01f * kl;

            g_cnt[b] = 0u;   // reset for next graph replay
        }
    }
}

extern "C" void kernel_launch(void* const* d_in, const int* in_sizes, int n_in,
                              void* d_out, int out_size)
{
    const float* kine_input  = (const float*)d_in[0];
    const float* class_input = (const float*)d_in[1];
    const float* kine_pred   = (const float*)d_in[2];
    const float* class_pred  = (const float*)d_in[3];
    const float* mu          = (const float*)d_in[4];
    const float* log_var     = (const float*)d_in[5];

    const int B = in_sizes[4] / LLAT;   // mu is [B, 32]

    nn_kernel<<<dim3(B, 2, 2), 128>>>(kine_input, class_input, kine_pred, class_pred,
                                      mu, log_var, (float*)d_out);
}

// round 12
// speedup vs baseline: 1.3396x; 1.0813x over previous
#include <cuda_runtime.h>
#include <math.h>

#define NPTS 512
#define DCLS 9
#define LLAT 32
#define MAXB 256
#define EF 20        // floats per entry (4 points SoA: x0-3,y0-3,z0-3,w0-3,c0-3) c = -0.5*|p|^2
#define CAND_HALF 256
#define ENT_HALF 64
#define CE 4         // entries per chunk (16 candidates)
#define NCHUNK1 16   // chunks per half
#define QPT 4

typedef unsigned long long u64;

// scratch: per (b, side, half, query): (partial unclamped dist, partial sdot); per (b, side) histogram
__device__ float2 g_ms[MAXB * 2 * 2 * NPTS];
__device__ int    g_hist[MAXB * 2 * DCLS];
__device__ unsigned int g_cnt[MAXB];   // zero-init; finisher resets each call

__device__ __forceinline__ u64 ffma2(u64 a, u64 b, u64 c) {
    u64 d; asm("fma.rn.f32x2 %0,%1,%2,%3;" : "=l"(d) : "l"(a), "l"(b), "l"(c)); return d;
}
__device__ __forceinline__ u64 pack2(float lo, float hi) {
    u64 r; asm("mov.b64 %0,{%1,%2};" : "=l"(r) : "f"(lo), "f"(hi)); return r;
}
__device__ __forceinline__ float2 unpack2(u64 v) {
    float2 r; asm("mov.b64 {%0,%1},%2;" : "=f"(r.x), "=f"(r.y) : "l"(v)); return r;
}

__device__ __forceinline__ float warpReduceSum(float v) {
    #pragma unroll
    for (int o = 16; o > 0; o >>= 1)
        v += __shfl_down_sync(0xFFFFFFFFu, v, o);
    return v;
}

// Rescan winning chunk (bit-identical score arithmetic) for first-occurrence local index.
__device__ __noinline__ int rescan_chunk(const float* __restrict__ sarr,
                                         int ch, float target, float4 q)
{
    const u64 qx = pack2(q.x, q.x), qy = pack2(q.y, q.y);
    const u64 qz = pack2(q.z, q.z), qw = pack2(q.w, q.w);
    const ulonglong2* cp = reinterpret_cast<const ulonglong2*>(sarr + ch * (CE * EF));
    int id = -1;
    #pragma unroll
    for (int e = 0; e < CE; e++) {
        ulonglong2 vx = cp[e * 5 + 0], vy = cp[e * 5 + 1], vz = cp[e * 5 + 2],
                   vw = cp[e * 5 + 3], vc = cp[e * 5 + 4];
        u64 s01 = ffma2(qx, vx.x, ffma2(qy, vy.x, ffma2(qz, vz.x, ffma2(qw, vw.x, vc.x))));
        u64 s23 = ffma2(qx, vx.y, ffma2(qy, vy.y, ffma2(qz, vz.y, ffma2(qw, vw.y, vc.y))));
        float2 a = unpack2(s01);
        float2 d = unpack2(s23);
        int base = ch * (CE * 4) + e * 4;
        if (id < 0 && a.x == target) id = base + 0;
        if (id < 0 && a.y == target) id = base + 1;
        if (id < 0 && d.x == target) id = base + 2;
        if (id < 0 && d.y == target) id = base + 3;
    }
    return (id < 0) ? 0 : id;
}

// grid = (B, 2 sides, 2 halves), block = 128. Last CTA per batch finalizes.
__global__ __launch_bounds__(128, 6) void nn_kernel(
    const float* __restrict__ kine_input,
    const float* __restrict__ class_input,
    const float* __restrict__ kine_pred,
    const float* __restrict__ class_pred,
    const float* __restrict__ mu,
    const float* __restrict__ log_var,
    float* __restrict__ out)
{
    const int b = blockIdx.x, side = blockIdx.y, half = blockIdx.z;
    const int t = threadIdx.x;

    const float* qk = (side == 0) ? kine_input : kine_pred;
    const float* ck = (side == 0) ? kine_pred  : kine_input;
    const float* cl = (side == 0) ? class_input : class_pred;  // own-side class rows
    const float* cg = (side == 0) ? class_pred  : class_input; // candidate-side class rows

    __shared__ __align__(16) float sc[ENT_HALF * EF];  // 5KB candidate half
    __shared__ int sh[DCLS];
    __shared__ unsigned int s_last;
    __shared__ float red[4];

    if (half == 0 && t < DCLS) sh[t] = 0;

    // ---- stage candidate half (2 points per thread), norm folded as -0.5*|p|^2 ----
    #pragma unroll
    for (int p = t; p < CAND_HALF; p += 128) {
        float4 v = reinterpret_cast<const float4*>(ck)[b * NPTS + half * CAND_HALF + p];
        float n = v.x * v.x + v.y * v.y + v.z * v.z + v.w * v.w;
        int e = p >> 2, l = p & 3;
        float* ba = sc + e * EF;
        ba[l] = v.x; ba[4 + l] = v.y; ba[8 + l] = v.z; ba[12 + l] = v.w;
        ba[16 + l] = -0.5f * n;
    }

    // ---- labels/histogram: only half-0 CTAs, own side's 512 class rows ----
    int lab[4];
    if (half == 0) {
        #pragma unroll
        for (int r = 0; r < 4; r++) {
            const float* row = cl + ((size_t)b * NPTS + t + 128 * r) * DCLS;
            int li = 0; float mi = row[0];
            #pragma unroll
            for (int d = 1; d < DCLS; d++) {
                float a = row[d];
                if (a > mi) { mi = a; li = d; }
            }
            lab[r] = li;
        }
    }

    __syncthreads();

    if (half == 0) {
        #pragma unroll
        for (int r = 0; r < 4; r++) atomicAdd(&sh[lab[r]], 1);
    }

    // ---- scan: 4 queries per thread over 256 candidates; argmax of score ----
    float gmax[QPT]; int gch[QPT];
    #pragma unroll
    for (int qi = 0; qi < QPT; qi++) { gmax[qi] = -3.402823466e38f; gch[qi] = 0; }

    {
        u64 qx[QPT], qy[QPT], qz[QPT], qw[QPT];
        #pragma unroll
        for (int qi = 0; qi < QPT; qi++) {
            float4 q = reinterpret_cast<const float4*>(qk)[b * NPTS + t + 128 * qi];
            qx[qi] = pack2(q.x, q.x); qy[qi] = pack2(q.y, q.y);
            qz[qi] = pack2(q.z, q.z); qw[qi] = pack2(q.w, q.w);
        }

        #pragma unroll 1
        for (int c = 0; c < NCHUNK1; c++) {
            float cm[QPT];
            #pragma unroll
            for (int qi = 0; qi < QPT; qi++) cm[qi] = -3.402823466e38f;
            const ulonglong2* cp = reinterpret_cast<const ulonglong2*>(sc + c * (CE * EF));
            #pragma unroll 2
            for (int e = 0; e < CE; e++) {
                ulonglong2 vx = cp[e * 5 + 0], vy = cp[e * 5 + 1], vz = cp[e * 5 + 2],
                           vw = cp[e * 5 + 3], vc = cp[e * 5 + 4];
                #pragma unroll
                for (int qi = 0; qi < QPT; qi++) {
                    u64 s01 = ffma2(qx[qi], vx.x, ffma2(qy[qi], vy.x, ffma2(qz[qi], vz.x, ffma2(qw[qi], vw.x, vc.x))));
                    u64 s23 = ffma2(qx[qi], vx.y, ffma2(qy[qi], vy.y, ffma2(qz[qi], vz.y, ffma2(qw[qi], vw.y, vc.y))));
                    float2 a = unpack2(s01);
                    float2 d = unpack2(s23);
                    cm[qi] = fmaxf(cm[qi], fmaxf(fmaxf(a.x, a.y), fmaxf(d.x, d.y)));
                }
            }
            #pragma unroll
            for (int qi = 0; qi < QPT; qi++)
                if (cm[qi] > gmax[qi]) { gmax[qi] = cm[qi]; gch[qi] = c; }
        }
    }   // packed queries die here

    // ---- epilogue: rescan for index, gather class rows, write (unclamped dist, sdot) ----
    const int slotbase = ((b * 2 + side) * 2 + half) * NPTS;
    #pragma unroll 1
    for (int qi = 0; qi < QPT; qi++) {
        float4 q = reinterpret_cast<const float4*>(qk)[b * NPTS + t + 128 * qi];
        float qn = q.x * q.x + q.y * q.y + q.z * q.z + q.w * q.w;
        int lidx = rescan_chunk(sc, gch[qi], gmax[qi], q);
        int gidx = half * CAND_HALF + lidx;

        const float* grow = cg + ((size_t)b * NPTS + gidx) * DCLS;
        const float* orow = cl + ((size_t)b * NPTS + t + 128 * qi) * DCLS;
        float sdot = 0.0f;
        #pragma unroll
        for (int d = 0; d < DCLS; d++) sdot = fmaf(grow[d], orow[d], sdot);

        float dist = fmaf(-2.0f, gmax[qi], qn);   // unclamped; monotone-decreasing in score
        g_ms[slotbase + t + 128 * qi] = make_float2(dist, sdot);
    }

    if (half == 0) {
        __syncthreads();
        if (t < DCLS) g_hist[(b * 2 + side) * DCLS + t] = sh[t];
    }

    // ---- last-CTA-per-batch finalization (4 CTAs per batch) ----
    __syncthreads();
    __threadfence();
    if (t == 0) s_last = atomicAdd(&g_cnt[b], 1u);
    __syncthreads();
    if (s_last != 3u) return;

    __threadfence();   // acquire

    // merge halves + reduce: 1024 (side,query) pairs, 8 per thread
    float r = 0.0f;
    #pragma unroll
    for (int j = 0; j < 8; j++) {
        int s = t + 128 * j;          // 0..1023
        int sd = s >> 9;
        int q = s & (NPTS - 1);
        int base = ((b * 2 + sd) * 2) * NPTS + q;
        float2 h0 = g_ms[base];
        float2 h1 = g_ms[base + NPTS];
        float m, sv;
        if (h0.x <= h1.x) { m = h0.x; sv = h0.y; } else { m = h1.x; sv = h1.y; }
        r += fmaxf(m, 0.0f) - sv;
    }

    const int lane = t & 31;
    const int wid  = t >> 5;
    float v = warpReduceSum(r);
    if (lane == 0) red[wid] = v;
    __syncthreads();
    if (wid == 0) {
        v = (lane < 4) ? red[lane] : 0.0f;
        v = warpReduceSum(v);
        if (lane == 0) {
            float S = v;

            const int* hi = g_hist + (b * 2 + 0) * DCLS;
            const int* hp = g_hist + (b * 2 + 1) * DCLS;
            float cn;
            {
                float d0 = fabsf((float)(hp[0] - hi[0]));
                float d8 = fabsf((float)(hp[DCLS - 1] - hi[DCLS - 1]));
                cn = d0 * 2.0f + d8 * 100.0f;
                #pragma unroll
                for (int c = 1; c < DCLS - 1; c++)
                    cn += fabsf((float)(hp[c] - hi[c]));
            }

            float kl = 0.0f;
            const float* mub = mu      + (size_t)b * LLAT;
            const float* lvb = log_var + (size_t)b * LLAT;
            #pragma unroll
            for (int l = 0; l < LLAT; l++) {
                float m  = mub[l];
                float lv = lvb[l];
                kl += 1.0f + lv - m * m - expf(lv);
            }
            kl = -0.5f * kl;

            out[b] = 0.99f * (S + 0.001f * cn) + 0.01f * kl;

            g_cnt[b] = 0u;   // reset for next graph replay
        }
    }
}

extern "C" void kernel_launch(void* const* d_in, const int* in_sizes, int n_in,
                              void* d_out, int out_size)
{
    const float* kine_input  = (const float*)d_in[0];
    const float* class_input = (const float*)d_in[1];
    const float* kine_pred   = (const float*)d_in[2];
    const float* class_pred  = (const float*)d_in[3];
    const float* mu          = (const float*)d_in[4];
    const float* log_var     = (const float*)d_in[5];

    const int B = in_sizes[4] / LLAT;   // mu is [B, 32]

    nn_kernel<<<dim3(B, 2, 2), 128>>>(kine_input, class_input, kine_pred, class_pred,
                                      mu, log_var, (float*)d_out);
}